// round 8
// baseline (speedup 1.0000x reference)
#include <cuda_runtime.h>
#include <cstdint>
#include <math.h>

#define HID   128
#define G4    512
#define OUTC  7
#define LEN   2048
#define BATCH 10
#define TPB   288   // 8 matvec warps (256 gate rows) + 1 control warp

// Packed fp32x2 FMA (Blackwell): 2 fp32 FMAs per lane per issue.
#define FMA2(d,a,b,c) asm("fma.rn.f32x2 %0, %1, %2, %3;" : "=l"(d) : "l"(a), "l"(b), "l"(c))

__device__ __forceinline__ unsigned smem_u32(const void* p) {
    return (unsigned)__cvta_generic_to_shared(p);
}
__device__ __forceinline__ unsigned my_ctarank() {
    unsigned r; asm("mov.u32 %0, %%cluster_ctarank;" : "=r"(r)); return r;
}
__device__ __forceinline__ unsigned mapa_u32(unsigned a, unsigned r) {
    unsigned o; asm("mapa.shared::cluster.u32 %0, %1, %2;" : "=r"(o) : "r"(a), "r"(r)); return o;
}
#define CLUSTER_SYNC() do { \
    asm volatile("barrier.cluster.arrive.aligned;" ::: "memory"); \
    asm volatile("barrier.cluster.wait.aligned;"   ::: "memory"); \
} while (0)

// MUFU-based activations (EX2/RCP): rel err ~1e-6, far inside 1e-3 budget.
__device__ __forceinline__ float fsig(float x) {
    return __fdividef(1.0f, 1.0f + __expf(-x));
}
__device__ __forceinline__ float ftanh(float x) {
    return 1.0f - __fdividef(2.0f, __expf(2.0f * x) + 1.0f);   // exact saturation
}

// 16 FMA2 pairs over one 64-wide half of h. W0 in {0,32}, H0 in {0,64}.
#define DOT_HALF(W0, H0) do {                                             \
    const float* hh = hb + (H0);                                          \
    _Pragma("unroll")                                                     \
    for (int q = 0; q < 16; q++) {                                        \
        ulonglong2 hv = *reinterpret_cast<const ulonglong2*>(hh + 4 * q); \
        FMA2(a0, w[(W0) + 2 * q],     hv.x, a0);                          \
        FMA2(a1, w[(W0) + 2 * q + 1], hv.y, a1);                          \
    } } while (0)

// 2-CTA cluster per batch element, unit-partitioned. Warp w of each CTA owns
// ALL FOUR gates of units 8w..8w+7 (lane = qg*8+ui), so activation -> cell is
// 3 intra-warp shuffles with no barrier; c lives in a register of lanes 0-7.
// The matvec is split: local-h half issued BEFORE the peer flag wait (hides
// DSMEM store latency), remote half after. Control warp overlaps step t-1
// softmax/argmax/sidx with step t's dot. 2 bar.sync per step.
__global__ void __cluster_dims__(2,1,1) __launch_bounds__(TPB, 1)
lstm_decode_kernel(const float* __restrict__ h0,      const float* __restrict__ c0,
                   const float* __restrict__ tgt_oh,  const unsigned* __restrict__ tf_mask,
                   const float* __restrict__ W_ih,    const float* __restrict__ W_hh,
                   const float* __restrict__ b_ih,    const float* __restrict__ b_hh,
                   const float* __restrict__ W_out,   const float* __restrict__ b_out,
                   float* __restrict__ out)
{
    __shared__ __align__(16) float h_sm[2][HID];     // indexed by global unit
    __shared__ float wih_t[OUTC * G4];               // W_ih transposed [c][row]
    __shared__ float wout_sm[OUTC * HID];
    __shared__ float bout_sm[OUTC];
    __shared__ float part_sm[2][16][OUTC];           // [buf][rank*8+warp][k]
    __shared__ int   sidx;
    __shared__ unsigned flag;                        // monotonic arrival counter
    __shared__ short tfidx_sm[LEN];

    const int      tid  = threadIdx.x;
    const unsigned rank = my_ctarank();
    const unsigned peer = rank ^ 1u;
    const int      b    = blockIdx.x >> 1;
    const bool     mv   = tid < 256;
    const int      wi   = tid >> 5;                  // warp 0..8
    const int      l    = tid & 31;
    const int      ui   = l & 7;                     // unit-in-warp
    const int      qg   = l >> 3;                    // gate 0..3 (i,f,g,o)
    const int      uu   = (int)rank * 64 + wi * 8 + ui;  // owned unit (mv only)
    const int      row  = qg * HID + uu;             // owned gate row

    // --- one-time setup -----------------------------------------------------
    unsigned long long w[64];                        // 128 weights packed f32x2
    float bias = 0.0f, c = 0.0f;
    if (mv) {
        const unsigned long long* wr = (const unsigned long long*)(W_hh + (size_t)row * HID);
        #pragma unroll
        for (int k = 0; k < 64; k++) w[k] = wr[k];
        bias = b_ih[row] + b_hh[row];
        if (l < 8) c = c0[b * HID + uu];             // c kept in register
    }
    for (int i = tid; i < OUTC * G4; i += TPB) {     // transpose W_ih
        int cc = i >> 9, r0 = i & 511;
        wih_t[i] = W_ih[r0 * OUTC + cc];
    }
    for (int i = tid; i < OUTC * HID; i += TPB) wout_sm[i] = W_out[i];
    if (tid < OUTC) bout_sm[tid] = b_out[tid];
    if (tid < HID) h_sm[0][tid] = h0[b * HID + tid];
    if (tid == 0) { sidx = OUTC - 1; flag = 0u; }
    for (int t = tid; t < LEN; t += TPB) {           // teacher-forcing indices
        short v = -1;
        if (tf_mask[t] != 0u) {
            v = 0;
            #pragma unroll
            for (int k = 0; k < OUTC; k++)
                if (tgt_oh[(t + 1) * OUTC + k] > 0.5f) v = (short)k;
        }
        tfidx_sm[t] = v;
    }
    __syncthreads();
    CLUSTER_SYNC();   // smem init visible cluster-wide before any remote op

    const unsigned flag_l = smem_u32(&flag);
    const unsigned flag_r = mapa_u32(flag_l, peer);
    const unsigned h_r0   = mapa_u32(smem_u32(&h_sm[0][0]), peer);
    const unsigned part_r = mapa_u32(smem_u32(&part_sm[0][0][0]), peer);

    // --- time loop: iteration t = matvec/cell of step t + control of t-1 ----
    for (int t = 0; t <= LEN; t++) {
        const float* hb = h_sm[t & 1];
        unsigned long long a0 = 0ull, a1 = 0ull;

        // A1: local-half dot — depends only on OWN CTA's h, no peer wait
        if (mv && t < LEN) {
            if (rank == 0) { DOT_HALF(0, 0);   } else { DOT_HALF(32, 64); }
        }

        // wait for peer's step t-1 exchange (64 release-adds/step)
        if (t > 0) {
            const unsigned target = (unsigned)t * 64u;
            unsigned v;
            do {
                asm volatile("ld.acquire.cluster.shared::cta.u32 %0, [%1];"
                             : "=r"(v) : "r"(flag_l));
            } while (v < target);
        }

        float p = 0.0f;
        if (mv && t < LEN) {
            // A2: remote-half dot over peer-written h
            if (rank == 0) { DOT_HALF(32, 64); } else { DOT_HALF(0, 0); }
            float2 f0 = *reinterpret_cast<float2*>(&a0);
            float2 f1 = *reinterpret_cast<float2*>(&a1);
            p = (f0.x + f0.y) + (f1.x + f1.y);
        }
        if (!mv && t > 0) {                          // control warp: step t-1
            const int t1 = (t - 1) & 1;
            float lv = -3.4e38f;
            if (l < OUTC) {
                lv = bout_sm[l];
                #pragma unroll
                for (int s = 0; s < 16; s++) lv += part_sm[t1][s][l];
            }
            float m = lv; int ai = (l < OUTC) ? l : 1000;
            #pragma unroll
            for (int off = 16; off; off >>= 1) {
                float om = __shfl_xor_sync(0xffffffffu, m, off);
                int   oi = __shfl_xor_sync(0xffffffffu, ai, off);
                if (om > m || (om == m && oi < ai)) { m = om; ai = oi; }
            }
            float e = (l < OUTC) ? __expf(lv - m) : 0.0f;
            float s = e;
            #pragma unroll
            for (int off = 16; off; off >>= 1) s += __shfl_xor_sync(0xffffffffu, s, off);
            if (l < OUTC && rank == 0) {
                float lg = __logf(s);
                out[((size_t)b * LEN + (t - 1)) * OUTC + l] = lv - m - lg;
            }
            if (l == 0) {                            // both CTAs: identical sidx
                int tv = tfidx_sm[t - 1];
                sidx = (tv >= 0) ? tv : ai;
            }
        }
        __syncthreads();   // sidx ready

        // B: gate value + activation + in-warp cell + exchange
        if (mv && t < LEN) {
            float gv = p + bias + wih_t[sidx * G4 + row];    // x is one-hot
            float a  = (qg == 2) ? ftanh(gv) : fsig(gv);
            float aF = __shfl_sync(0xffffffffu, a, ui + 8);
            float aG = __shfl_sync(0xffffffffu, a, ui + 16);
            float aO = __shfl_sync(0xffffffffu, a, ui + 24);
            if (l < 8) {                             // lane owns unit uu
                float c2 = aF * c + a * aG;          // a == aI here
                float h2 = aO * ftanh(c2);
                c = c2;
                h_sm[(t + 1) & 1][uu] = h2;
                unsigned hr = h_r0 + (unsigned)((((t + 1) & 1) * HID + uu) * 4);
                asm volatile("st.shared::cluster.f32 [%0], %1;" :: "r"(hr), "f"(h2) : "memory");

                float pk[OUTC];
                #pragma unroll
                for (int k = 0; k < OUTC; k++) pk[k] = h2 * wout_sm[k * HID + uu];
                #pragma unroll
                for (int k = 0; k < OUTC; k++) {
                    #pragma unroll
                    for (int off = 4; off; off >>= 1)
                        pk[k] += __shfl_xor_sync(0xFFu, pk[k], off);
                }
                if (ui == 0) {
                    const int s8 = (int)rank * 8 + wi;
                    #pragma unroll
                    for (int k = 0; k < OUTC; k++) {
                        part_sm[t & 1][s8][k] = pk[k];
                        unsigned pr = part_r + (unsigned)((((t & 1) * 16 + s8) * OUTC + k) * 4);
                        asm volatile("st.shared::cluster.f32 [%0], %1;" :: "r"(pr), "f"(pk[k]) : "memory");
                    }
                }
                // release this thread's remote stores; count arrival on peer
                asm volatile("red.release.cluster.shared::cluster.add.u32 [%0], %1;"
                             :: "r"(flag_r), "r"(1u) : "memory");
            }
        }
        __syncthreads();   // local h2/partials visible for next iteration
    }

    // final states (LEN even -> h in buffer 0); c is in registers of lanes 0-7
    if (mv && l < 8) {
        out[(size_t)BATCH * LEN * OUTC + b * HID + uu]               = h_sm[LEN & 1][uu];
        out[(size_t)BATCH * LEN * OUTC + BATCH * HID + b * HID + uu] = c;
    }
    CLUSTER_SYNC();   // keep smem alive until peer's last remote ops land
}

extern "C" void kernel_launch(void* const* d_in, const int* in_sizes, int n_in,
                              void* d_out, int out_size)
{
    (void)in_sizes; (void)n_in; (void)out_size;
    lstm_decode_kernel<<<BATCH * 2, TPB>>>(
        (const float*)d_in[0], (const float*)d_in[1], (const float*)d_in[2],
        (const unsigned*)d_in[3], (const float*)d_in[4], (const float*)d_in[5],
        (const float*)d_in[6], (const float*)d_in[7], (const float*)d_in[8],
        (const float*)d_in[9], (float*)d_out);
}

// round 10
// speedup vs baseline: 1.0054x; 1.0054x over previous
#include <cuda_runtime.h>
#include <cstdint>
#include <math.h>

#define HID   128
#define G4    512
#define OUTC  7
#define LEN   2048
#define BATCH 10
#define TPB   288   // 8 matvec warps (256 gate rows) + 1 control warp

// Packed fp32x2 FMA (Blackwell): 2 fp32 FMAs per lane per issue.
#define FMA2(d,a,b,c) asm("fma.rn.f32x2 %0, %1, %2, %3;" : "=l"(d) : "l"(a), "l"(b), "l"(c))

__device__ __forceinline__ unsigned smem_u32(const void* p) {
    return (unsigned)__cvta_generic_to_shared(p);
}
__device__ __forceinline__ unsigned my_ctarank() {
    unsigned r; asm("mov.u32 %0, %%cluster_ctarank;" : "=r"(r)); return r;
}
__device__ __forceinline__ unsigned mapa_u32(unsigned a, unsigned r) {
    unsigned o; asm("mapa.shared::cluster.u32 %0, %1, %2;" : "=r"(o) : "r"(a), "r"(r)); return o;
}
#define CLUSTER_SYNC() do { \
    asm volatile("barrier.cluster.arrive.aligned;" ::: "memory"); \
    asm volatile("barrier.cluster.wait.aligned;"   ::: "memory"); \
} while (0)

// Wait (HW sleep) on local mbarrier phase, cluster-scope acquire so peer's
// release-arrive makes its DSMEM h-stores visible.
#define MBAR_WAIT_CL(addr, parity) do {                                          \
    unsigned _done;                                                              \
    do {                                                                         \
        asm volatile("{\n\t.reg .pred p;\n\t"                                    \
            "mbarrier.try_wait.parity.acquire.cluster.shared::cta.b64 p, [%1], %2, 0x989680;\n\t" \
            "selp.b32 %0, 1, 0, p;\n\t}"                                         \
            : "=r"(_done) : "r"(addr), "r"(parity) : "memory");                  \
    } while (!_done);                                                            \
} while (0)

// MUFU-based activations (EX2/RCP): rel err ~1e-6, far inside 1e-3 budget.
__device__ __forceinline__ float fsig(float x) {
    return __fdividef(1.0f, 1.0f + __expf(-x));
}
__device__ __forceinline__ float ftanh(float x) {
    return 1.0f - __fdividef(2.0f, __expf(2.0f * x) + 1.0f);   // exact saturation
}

// 16 FMA2 pairs over one 64-wide half of h. W0 in {0,32}, H0 in {0,64}.
#define DOT_HALF(W0, H0) do {                                             \
    const float* hh = hb + (H0);                                          \
    _Pragma("unroll")                                                     \
    for (int q = 0; q < 16; q++) {                                        \
        ulonglong2 hv = *reinterpret_cast<const ulonglong2*>(hh + 4 * q); \
        FMA2(a0, w[(W0) + 2 * q],     hv.x, a0);                          \
        FMA2(a1, w[(W0) + 2 * q + 1], hv.y, a1);                          \
    } } while (0)

// 2-CTA cluster per batch element, unit-partitioned (R7 layout, which passed).
// Per-step cross-CTA traffic: 64 remote h2 stores + 64 mbarrier release-arrives
// on the peer's ping-pong mbarrier (SYNCS pipe — replaces 64 serialized remote
// ATOMS on one flag word). No partial-logit exchange: the control warp
// recomputes the 7 logits straight from h(t-1) in smem, overlapped with the
// matvec. sidx handoff via tagged smem word. ONE __syncthreads per step.
__global__ void __cluster_dims__(2,1,1) __launch_bounds__(TPB, 1)
lstm_decode_kernel(const float* __restrict__ h0,      const float* __restrict__ c0,
                   const float* __restrict__ tgt_oh,  const unsigned* __restrict__ tf_mask,
                   const float* __restrict__ W_ih,    const float* __restrict__ W_hh,
                   const float* __restrict__ b_ih,    const float* __restrict__ b_hh,
                   const float* __restrict__ W_out,   const float* __restrict__ b_out,
                   float* __restrict__ out)
{
    __shared__ __align__(16) float h_sm[3][HID];     // triple-buffered h
    __shared__ float wih_t[OUTC * G4];               // W_ih transposed [c][row]
    __shared__ float wout_sm[OUTC * HID];
    __shared__ float bout_sm[OUTC];
    __shared__ __align__(8) unsigned long long mbar[2];  // ping-pong, count=64
    __shared__ unsigned sidx_word;                   // (tag<<3)|sidx
    __shared__ short tfidx_sm[LEN];

    const int      tid  = threadIdx.x;
    const unsigned rank = my_ctarank();
    const unsigned peer = rank ^ 1u;
    const int      b    = blockIdx.x >> 1;
    const bool     mv   = tid < 256;
    const int      wi   = tid >> 5;                  // warp 0..8
    const int      l    = tid & 31;
    const int      ui   = l & 7;                     // unit-in-warp
    const int      qg   = l >> 3;                    // gate 0..3 (i,f,g,o)
    const int      uu   = (int)rank * 64 + wi * 8 + ui;  // owned unit (mv only)
    const int      row  = qg * HID + uu;             // owned gate row

    // --- one-time setup -----------------------------------------------------
    unsigned long long w[64];                        // 128 weights packed f32x2
    float bias = 0.0f, c = 0.0f;
    if (mv) {
        const unsigned long long* wr = (const unsigned long long*)(W_hh + (size_t)row * HID);
        #pragma unroll
        for (int k = 0; k < 64; k++) w[k] = wr[k];
        bias = b_ih[row] + b_hh[row];
        if (l < 8) c = c0[b * HID + uu];             // c kept in register
    }
    for (int i = tid; i < OUTC * G4; i += TPB) {     // transpose W_ih
        int cc = i >> 9, r0 = i & 511;
        wih_t[i] = W_ih[r0 * OUTC + cc];
    }
    for (int i = tid; i < OUTC * HID; i += TPB) wout_sm[i] = W_out[i];
    if (tid < OUTC) bout_sm[tid] = b_out[tid];
    if (tid < HID) h_sm[0][tid] = h0[b * HID + tid];
    if (tid == 0) {
        sidx_word = (unsigned)(OUTC - 1);            // tag 0, x0 = one-hot OUT-1
        asm volatile("mbarrier.init.shared.b64 [%0], %1;" :: "r"(smem_u32(&mbar[0])), "r"(64u) : "memory");
        asm volatile("mbarrier.init.shared.b64 [%0], %1;" :: "r"(smem_u32(&mbar[1])), "r"(64u) : "memory");
    }
    for (int t = tid; t < LEN; t += TPB) {           // teacher-forcing indices
        short v = -1;
        if (tf_mask[t] != 0u) {
            v = 0;
            #pragma unroll
            for (int k = 0; k < OUTC; k++)
                if (tgt_oh[(t + 1) * OUTC + k] > 0.5f) v = (short)k;
        }
        tfidx_sm[t] = v;
    }
    __syncthreads();
    CLUSTER_SYNC();   // smem/mbar init visible cluster-wide before any remote op

    const unsigned mb_l0 = smem_u32(&mbar[0]);
    const unsigned mb_r0 = mapa_u32(mb_l0, peer);
    const unsigned h_r0  = mapa_u32(smem_u32(&h_sm[0][0]), peer);
    volatile unsigned* sw = &sidx_word;

    int cur3 = 0, nxt3 = 1;                          // h buffers: read cur3, write nxt3

    // --- time loop: iteration t = matvec/cell of step t + control of t-1 ----
    for (int t = 0; t <= LEN; t++) {
        const float* hb = h_sm[cur3];
        unsigned long long a0 = 0ull, a1 = 0ull;

        // A1: local-half dot — depends only on OWN CTA's h, no peer wait
        if (mv && t < LEN) {
            if (rank == 0) { DOT_HALF(0, 0);   } else { DOT_HALF(32, 64); }
        }

        // wait for peer's step t-1 h exchange (64 release-arrives)
        if (t > 0) {
            MBAR_WAIT_CL(mb_l0 + (((t - 1) & 1) << 3), ((t - 1) >> 1) & 1);
        }

        float p = 0.0f;
        if (mv && t < LEN) {
            // A2: remote-half dot over peer-written h
            if (rank == 0) { DOT_HALF(32, 64); } else { DOT_HALF(0, 0); }
            float2 f0 = *reinterpret_cast<float2*>(&a0);
            float2 f1 = *reinterpret_cast<float2*>(&a1);
            p = (f0.x + f0.y) + (f1.x + f1.y);
        }
        if (!mv && t > 0) {                          // control warp: step t-1
            // logits(t-1) = h(t-1) . W_out^T + b_out, computed in-warp
            float hj[4];
            #pragma unroll
            for (int q = 0; q < 4; q++) hj[q] = hb[l + 32 * q];
            float pk[OUTC];
            #pragma unroll
            for (int k = 0; k < OUTC; k++) {
                float s = 0.0f;
                #pragma unroll
                for (int q = 0; q < 4; q++)
                    s = fmaf(hj[q], wout_sm[k * HID + l + 32 * q], s);
                #pragma unroll
                for (int off = 16; off; off >>= 1)
                    s += __shfl_xor_sync(0xffffffffu, s, off);   // all lanes get sum
                pk[k] = s;
            }
            float lv = -3.4e38f;
            if (l < OUTC) {
                float v = pk[0];
                if (l == 1) v = pk[1];
                if (l == 2) v = pk[2];
                if (l == 3) v = pk[3];
                if (l == 4) v = pk[4];
                if (l == 5) v = pk[5];
                if (l == 6) v = pk[6];
                lv = v + bout_sm[l];
            }
            float m = lv; int ai = (l < OUTC) ? l : 1000;
            #pragma unroll
            for (int off = 16; off; off >>= 1) {
                float om = __shfl_xor_sync(0xffffffffu, m, off);
                int   oi = __shfl_xor_sync(0xffffffffu, ai, off);
                if (om > m || (om == m && oi < ai)) { m = om; ai = oi; }
            }
            float e = (l < OUTC) ? __expf(lv - m) : 0.0f;
            float s2 = e;
            #pragma unroll
            for (int off = 16; off; off >>= 1) s2 += __shfl_xor_sync(0xffffffffu, s2, off);
            if (l < OUTC && rank == 0) {
                float lg = __logf(s2);
                out[((size_t)b * LEN + (t - 1)) * OUTC + l] = lv - m - lg;
            }
            if (l == 0) {                            // publish x(t) index, tag t
                int tv = tfidx_sm[t - 1];
                int si = (tv >= 0) ? tv : ai;
                *sw = ((unsigned)t << 3) | (unsigned)si;
            }
        }

        // B: gate value + activation + in-warp cell + exchange
        if (mv && t < LEN) {
            unsigned v;                              // spin for sidx tag == t
            do { v = *sw; } while ((v >> 3) != (unsigned)t);
            const int cur = (int)(v & 7u);
            float gv = p + bias + wih_t[cur * G4 + row];     // x is one-hot
            float a  = (qg == 2) ? ftanh(gv) : fsig(gv);
            float aF = __shfl_sync(0xffffffffu, a, ui + 8);
            float aG = __shfl_sync(0xffffffffu, a, ui + 16);
            float aO = __shfl_sync(0xffffffffu, a, ui + 24);
            if (l < 8) {                             // lane owns unit uu
                float c2 = aF * c + a * aG;          // a == aI here
                float h2 = aO * ftanh(c2);
                c = c2;
                h_sm[nxt3][uu] = h2;
                unsigned hr = h_r0 + (unsigned)((nxt3 * HID + uu) * 4);
                asm volatile("st.shared::cluster.f32 [%0], %1;" :: "r"(hr), "f"(h2) : "memory");
                // release-arrive on PEER's ping-pong mbarrier (orders the store)
                asm volatile("mbarrier.arrive.release.cluster.shared::cluster.b64 _, [%0];"
                             :: "r"(mb_r0 + ((t & 1) << 3)) : "memory");
            }
        }
        __syncthreads();   // one bar/step: h_sm[nxt3] + control reads settled

        cur3 = nxt3; nxt3 = (nxt3 == 2) ? 0 : nxt3 + 1;
    }

    // final states: h(LEN-1) is in buffer written at t=LEN-1; after the last
    // rotation cur3 points one past it — recompute directly: LEN % 3.
    if (mv && l < 8) {
        out[(size_t)BATCH * LEN * OUTC + b * HID + uu]               = h_sm[LEN % 3][uu];
        out[(size_t)BATCH * LEN * OUTC + BATCH * HID + b * HID + uu] = c;
    }
    CLUSTER_SYNC();   // keep smem alive until peer's last remote ops land
}

extern "C" void kernel_launch(void* const* d_in, const int* in_sizes, int n_in,
                              void* d_out, int out_size)
{
    (void)in_sizes; (void)n_in; (void)out_size;
    lstm_decode_kernel<<<BATCH * 2, TPB>>>(
        (const float*)d_in[0], (const float*)d_in[1], (const float*)d_in[2],
        (const unsigned*)d_in[3], (const float*)d_in[4], (const float*)d_in[5],
        (const float*)d_in[6], (const float*)d_in[7], (const float*)d_in[8],
        (const float*)d_in[9], (float*)d_out);
}